// round 2
// baseline (speedup 1.0000x reference)
#include <cuda_runtime.h>
#include <cstdint>

#define T_STEPS 100
#define D_IN 16
#define H_DIM 32
#define HD 50
#define N_EULER 10
#define DT_SCALER (1.0f/24.0f)
#define STEP_F 0.1f
#define WARPS 4          // warps per CTA
#define RB 4             // batches per warp

__device__ __forceinline__ float tanh_fast(float v) {
    float r;
    asm("tanh.approx.f32 %0, %1;" : "=f"(r) : "f"(v));
    return r;
}

// packed fp32x2 fma: d = a*b + c elementwise on two packed floats
__device__ __forceinline__ unsigned long long ffma2(unsigned long long a,
                                                    unsigned long long b,
                                                    unsigned long long c) {
    unsigned long long d;
    asm("fma.rn.f32x2 %0, %1, %2, %3;" : "=l"(d) : "l"(a), "l"(b), "l"(c));
    return d;
}

__device__ __forceinline__ float f2_sum(unsigned long long v) {
    float lo, hi;
    asm("mov.b64 {%0, %1}, %2;" : "=f"(lo), "=f"(hi) : "l"(v));
    return lo + hi;
}

__global__ void __launch_bounds__(WARPS * 32)
latode2_kernel(const float* __restrict__ dt, const float* __restrict__ x,
               const float* __restrict__ W1, const float* __restrict__ b1,
               const float* __restrict__ W2, const float* __restrict__ b2,
               const float* __restrict__ W3, const float* __restrict__ b3,
               const float* __restrict__ W4, const float* __restrict__ b4,
               float* __restrict__ out, int B)
{
    // Row strides 52 / 52 / 36 floats: 13 / 13 / 9 in 16B units (odd mod 8)
    // -> lane-varying LDS.128 hits the 4-wavefront conflict-free minimum.
    __shared__ __align__(16) float W1s[64][52];   // rows 50..63 zero, cols 48..51 zero
    __shared__ __align__(16) float W2s[32][52];   // cols 50,51 zero
    __shared__ __align__(16) float W3s[64][36];   // cols 32..35 zero
    __shared__ __align__(16) float W4s[64];
    __shared__ __align__(16) float b1s[64];       // 50..63 zero
    __shared__ __align__(16) float b2s[32];
    __shared__ __align__(16) float b3s[64];
    __shared__ float b4s;
    __shared__ __align__(16) float in_sh[WARPS][RB][48];   // [x(16) ; h(32)]
    __shared__ __align__(16) float t1_sh[WARPS][RB][64];

    const int tid  = threadIdx.x;
    const int nthr = WARPS * 32;

    for (int i = tid; i < 64 * 52; i += nthr) {
        int r = i / 52, c = i - r * 52;
        W1s[r][c] = (r < HD && c < 48) ? W1[r * 48 + c] : 0.0f;
    }
    for (int i = tid; i < 32 * 52; i += nthr) {
        int r = i / 52, c = i - r * 52;
        W2s[r][c] = (c < HD) ? W2[r * HD + c] : 0.0f;
    }
    for (int i = tid; i < 64 * 36; i += nthr) {
        int r = i / 36, c = i - r * 36;
        W3s[r][c] = (c < H_DIM) ? W3[r * H_DIM + c] : 0.0f;
    }
    if (tid < 64) {
        W4s[tid] = W4[tid];
        b1s[tid] = (tid < HD) ? b1[tid] : 0.0f;
        b3s[tid] = b3[tid];
    }
    if (tid < 32) b2s[tid] = b2[tid];
    if (tid == 0) b4s = b4[0];
    __syncthreads();

    const int warp = tid >> 5;
    const int lane = tid & 31;
    const long wg  = (long)blockIdx.x * WARPS + warp;   // global warp id
    const long b0  = wg * RB;
    if (b0 >= B) return;                                // warp-uniform

    long bi[RB];
    #pragma unroll
    for (int r = 0; r < RB; ++r) {
        long bb = b0 + r;
        bi[r] = (bb < B) ? bb : (B - 1);                // clamp (redundant work, valid mem)
    }

    float (*insh)[48] = in_sh[warp];
    float (*t1s)[64]  = t1_sh[warp];

    const float bias1a = b1s[lane];
    const float bias1b = b1s[lane + 32];
    const float bias2  = b2s[lane];
    const float bias3a = b3s[lane];
    const float bias3b = b3s[lane + 32];
    const float w4a    = W4s[lane];
    const float w4b    = W4s[lane + 32];
    const float bias4  = b4s;

    float h[RB], y[RB], scale[RB];
    #pragma unroll
    for (int r = 0; r < RB; ++r) h[r] = 0.0f;

    for (int t = 0; t < T_STEPS; ++t) {
        #pragma unroll
        for (int r = 0; r < RB; ++r) {
            const float* xr = x + (size_t)bi[r] * T_STEPS * D_IN + (size_t)t * D_IN;
            if (lane < D_IN) insh[r][lane] = xr[lane];
            const float* dr = dt + (size_t)bi[r] * T_STEPS * 2 + (size_t)t * 2;
            scale[r] = (dr[1] - dr[0]) * DT_SCALER;     // uniform LDG, cached
            y[r] = xr[0];                               // y0 = x[b,t,0]
        }
        __syncwarp();

        for (int e = 0; e < N_EULER; ++e) {
            #pragma unroll
            for (int r = 0; r < RB; ++r) insh[r][D_IN + lane] = h[r];   // publish h_old
            __syncwarp();

            // ---- layer 1: z1[j] = tanh(W1[j,:] . [x;h] + b1[j]); rows lane, lane+32
            unsigned long long a0[RB], a1[RB];
            #pragma unroll
            for (int r = 0; r < RB; ++r) { a0[r] = 0ULL; a1[r] = 0ULL; }
            #pragma unroll
            for (int kk = 0; kk < 12; ++kk) {
                ulonglong2 w0 = *(const ulonglong2*)&W1s[lane][kk * 4];
                ulonglong2 w1 = *(const ulonglong2*)&W1s[lane + 32][kk * 4];
                #pragma unroll
                for (int r = 0; r < RB; ++r) {
                    ulonglong2 iv = *(const ulonglong2*)&insh[r][kk * 4];  // uniform -> bcast
                    a0[r] = ffma2(w0.x, iv.x, a0[r]);
                    a0[r] = ffma2(w0.y, iv.y, a0[r]);
                    a1[r] = ffma2(w1.x, iv.x, a1[r]);
                    a1[r] = ffma2(w1.y, iv.y, a1[r]);
                }
            }
            #pragma unroll
            for (int r = 0; r < RB; ++r) {
                t1s[r][lane]      = tanh_fast(f2_sum(a0[r]) + bias1a);
                t1s[r][lane + 32] = tanh_fast(f2_sum(a1[r]) + bias1b); // pad rows -> 0
            }
            __syncwarp();

            // ---- layer 2: dh[i] = tanh(W2[i,:] . t1 + b2[i]) * scale
            unsigned long long a2[RB];
            #pragma unroll
            for (int r = 0; r < RB; ++r) a2[r] = 0ULL;
            #pragma unroll
            for (int kk = 0; kk < 13; ++kk) {
                ulonglong2 w = *(const ulonglong2*)&W2s[lane][kk * 4];
                #pragma unroll
                for (int r = 0; r < RB; ++r) {
                    ulonglong2 iv = *(const ulonglong2*)&t1s[r][kk * 4];
                    a2[r] = ffma2(w.x, iv.x, a2[r]);
                    a2[r] = ffma2(w.y, iv.y, a2[r]);
                }
            }

            // ---- layer 3: t3[j] = tanh(W3[j,:] . h_old + b3[j]); h_old in insh[r][16..47]
            unsigned long long a3[RB], a4[RB];
            #pragma unroll
            for (int r = 0; r < RB; ++r) { a3[r] = 0ULL; a4[r] = 0ULL; }
            #pragma unroll
            for (int kk = 0; kk < 8; ++kk) {
                ulonglong2 w0 = *(const ulonglong2*)&W3s[lane][kk * 4];
                ulonglong2 w1 = *(const ulonglong2*)&W3s[lane + 32][kk * 4];
                #pragma unroll
                for (int r = 0; r < RB; ++r) {
                    ulonglong2 iv = *(const ulonglong2*)&insh[r][D_IN + kk * 4];
                    a3[r] = ffma2(w0.x, iv.x, a3[r]);
                    a3[r] = ffma2(w0.y, iv.y, a3[r]);
                    a4[r] = ffma2(w1.x, iv.x, a4[r]);
                    a4[r] = ffma2(w1.y, iv.y, a4[r]);
                }
            }

            // ---- layer 4 + state update
            #pragma unroll
            for (int r = 0; r < RB; ++r) {
                const float dh = tanh_fast(f2_sum(a2[r]) + bias2) * scale[r];
                float p = fmaf(w4a, tanh_fast(f2_sum(a3[r]) + bias3a),
                               w4b * tanh_fast(f2_sum(a4[r]) + bias3b));
                p += __shfl_xor_sync(0xffffffffu, p, 16);
                p += __shfl_xor_sync(0xffffffffu, p, 8);
                p += __shfl_xor_sync(0xffffffffu, p, 4);
                p += __shfl_xor_sync(0xffffffffu, p, 2);
                p += __shfl_xor_sync(0xffffffffu, p, 1);
                const float dy = (p + bias4) * scale[r];
                y[r] = fmaf(STEP_F, dy, y[r]);
                h[r] = fmaf(STEP_F, dh, h[r]);
            }
            __syncwarp();   // all reads of insh/t1s done before next-iter writes
        }

        if (lane == 0) {
            #pragma unroll
            for (int r = 0; r < RB; ++r)
                if (b0 + r < B) out[(size_t)(b0 + r) * T_STEPS + t] = y[r];
        }
        __syncwarp();
    }
}

extern "C" void kernel_launch(void* const* d_in, const int* in_sizes, int n_in,
                              void* d_out, int out_size)
{
    const float* dt = (const float*)d_in[0];
    const float* x  = (const float*)d_in[1];
    const float* W1 = (const float*)d_in[2];
    const float* b1 = (const float*)d_in[3];
    const float* W2 = (const float*)d_in[4];
    const float* b2 = (const float*)d_in[5];
    const float* W3 = (const float*)d_in[6];
    const float* b3 = (const float*)d_in[7];
    const float* W4 = (const float*)d_in[8];
    const float* b4 = (const float*)d_in[9];
    float* out = (float*)d_out;

    const int B = in_sizes[1] / (T_STEPS * D_IN);   // x has B*T*D elements
    const int batches_per_cta = WARPS * RB;
    const int grid = (B + batches_per_cta - 1) / batches_per_cta;
    latode2_kernel<<<grid, WARPS * 32>>>(dt, x, W1, b1, W2, b2, W3, b3,
                                         W4, b4, out, B);
}

// round 3
// speedup vs baseline: 1.7979x; 1.7979x over previous
#include <cuda_runtime.h>

#define T_STEPS 100
#define D_IN 16
#define N_EULER 10
#define DT_SCALER (1.0f/24.0f)
#define STEP_F 0.1f
#define WARPS 4          // warps per CTA
#define RB 8             // batches per warp

typedef unsigned long long u64;

__device__ __forceinline__ float tanh_fast(float v) {
    float r;
    asm("tanh.approx.f32 %0, %1;" : "=f"(r) : "f"(v));
    return r;
}
// packed fp32x2 fma: d = a*b + c on two packed floats
__device__ __forceinline__ u64 ffma2(u64 a, u64 b, u64 c) {
    u64 d;
    asm("fma.rn.f32x2 %0, %1, %2, %3;" : "=l"(d) : "l"(a), "l"(b), "l"(c));
    return d;
}
__device__ __forceinline__ u64 pack2(float lo, float hi) {
    u64 d;
    asm("mov.b64 %0, {%1, %2};" : "=l"(d) : "f"(lo), "f"(hi));
    return d;
}
__device__ __forceinline__ float f2_sum(u64 v) {
    float lo, hi;
    asm("mov.b64 {%0, %1}, %2;" : "=f"(lo), "=f"(hi) : "l"(v));
    return lo + hi;
}

__global__ void __launch_bounds__(WARPS * 32)
latode2_kernel(const float* __restrict__ dt, const float* __restrict__ x,
               const float* __restrict__ W1, const float* __restrict__ b1,
               const float* __restrict__ W2, const float* __restrict__ b2,
               const float* __restrict__ W3, const float* __restrict__ b3,
               const float* __restrict__ W4, const float* __restrict__ b4,
               float* __restrict__ out, int B)
{
    // SoA even/odd weight layout: lane j reads column j -> coalesced LDS.32,
    // 1 wavefront each (no within-instruction replay of wide LDS).
    __shared__ float W1e[24][64], W1o[24][64];   // rows (j) 50..63 zero
    __shared__ float W2e[26][32], W2o[26][32];   // k2=25 zero (k=50,51 pad)
    __shared__ float W3e[16][64], W3o[16][64];
    __shared__ float W4s[64], b1s[64], b2s[32], b3s[64];
    __shared__ float b4s;
    __shared__ __align__(16) float in_sh[WARPS][RB][48];   // [x(16) ; h(32)]
    __shared__ __align__(16) float t1_sh[WARPS][RB][64];

    const int tid  = threadIdx.x;
    const int nthr = WARPS * 32;

    for (int i = tid; i < 24 * 64; i += nthr) {
        int k2 = i >> 6, j = i & 63;
        W1e[k2][j] = (j < 50) ? W1[j * 48 + 2 * k2]     : 0.0f;
        W1o[k2][j] = (j < 50) ? W1[j * 48 + 2 * k2 + 1] : 0.0f;
    }
    for (int i = tid; i < 26 * 32; i += nthr) {
        int k2 = i >> 5, j = i & 31;
        W2e[k2][j] = (2 * k2     < 50) ? W2[j * 50 + 2 * k2]     : 0.0f;
        W2o[k2][j] = (2 * k2 + 1 < 50) ? W2[j * 50 + 2 * k2 + 1] : 0.0f;
    }
    for (int i = tid; i < 16 * 64; i += nthr) {
        int k2 = i >> 6, j = i & 63;
        W3e[k2][j] = W3[j * 32 + 2 * k2];
        W3o[k2][j] = W3[j * 32 + 2 * k2 + 1];
    }
    if (tid < 64) {
        W4s[tid] = W4[tid];
        b1s[tid] = (tid < 50) ? b1[tid] : 0.0f;
        b3s[tid] = b3[tid];
    }
    if (tid < 32) b2s[tid] = b2[tid];
    if (tid == 0) b4s = b4[0];
    __syncthreads();

    const int warp = tid >> 5;
    const int lane = tid & 31;
    const long wg  = (long)blockIdx.x * WARPS + warp;
    const long b0  = wg * RB;
    if (b0 >= B) return;   // warp-uniform

    long bi[RB];
    #pragma unroll
    for (int r = 0; r < RB; ++r) {
        long bb = b0 + r;
        bi[r] = (bb < B) ? bb : (B - 1);
    }

    float (*insh)[48] = in_sh[warp];
    float (*t1s)[64]  = t1_sh[warp];

    const float bias1a = b1s[lane];
    const float bias1b = b1s[lane + 32];
    const float bias2  = b2s[lane];
    const float bias3a = b3s[lane];
    const float bias3b = b3s[lane + 32];
    const float w4a    = W4s[lane];
    const float w4b    = W4s[lane + 32];
    const float bias4  = b4s;

    float h[RB], y[RB], scale[RB];
    #pragma unroll
    for (int r = 0; r < RB; ++r) h[r] = 0.0f;

    #pragma unroll 1
    for (int t = 0; t < T_STEPS; ++t) {
        #pragma unroll
        for (int r = 0; r < RB; ++r) {
            const float* xr = x + (size_t)bi[r] * T_STEPS * D_IN + (size_t)t * D_IN;
            if (lane < D_IN) insh[r][lane] = xr[lane];
            const float* dr = dt + (size_t)bi[r] * T_STEPS * 2 + (size_t)t * 2;
            scale[r] = (dr[1] - dr[0]) * DT_SCALER;
            y[r] = xr[0];
        }
        __syncwarp();

        #pragma unroll 1
        for (int e = 0; e < N_EULER; ++e) {
            #pragma unroll
            for (int r = 0; r < RB; ++r) insh[r][D_IN + lane] = h[r];  // publish h_old
            __syncwarp();

            // ---- layer 1: t1[j] = tanh(W1[j,:].[x;h] + b1[j]); rows lane, lane+32
            u64 a0[RB], a1[RB];
            #pragma unroll
            for (int r = 0; r < RB; ++r) {
                a0[r] = pack2(bias1a, 0.0f);
                a1[r] = pack2(bias1b, 0.0f);
            }
            #pragma unroll
            for (int kk = 0; kk < 12; ++kk) {
                u64 w0a = pack2(W1e[2*kk  ][lane],      W1o[2*kk  ][lane]);
                u64 w0b = pack2(W1e[2*kk+1][lane],      W1o[2*kk+1][lane]);
                u64 w1a = pack2(W1e[2*kk  ][lane + 32], W1o[2*kk  ][lane + 32]);
                u64 w1b = pack2(W1e[2*kk+1][lane + 32], W1o[2*kk+1][lane + 32]);
                #pragma unroll
                for (int r = 0; r < RB; ++r) {
                    ulonglong2 iv = *(const ulonglong2*)&insh[r][4 * kk];  // uniform -> bcast
                    a0[r] = ffma2(w0a, iv.x, a0[r]);
                    a0[r] = ffma2(w0b, iv.y, a0[r]);
                    a1[r] = ffma2(w1a, iv.x, a1[r]);
                    a1[r] = ffma2(w1b, iv.y, a1[r]);
                }
            }
            #pragma unroll
            for (int r = 0; r < RB; ++r) {
                t1s[r][lane]      = tanh_fast(f2_sum(a0[r]));
                t1s[r][lane + 32] = tanh_fast(f2_sum(a1[r]));  // pad rows -> tanh(0)=0
            }
            __syncwarp();

            // ---- layer 2: dh[i] = tanh(W2[i,:].t1 + b2[i]) * scale
            u64 a2[RB];
            #pragma unroll
            for (int r = 0; r < RB; ++r) a2[r] = pack2(bias2, 0.0f);
            #pragma unroll
            for (int kk = 0; kk < 13; ++kk) {
                u64 wa = pack2(W2e[2*kk  ][lane], W2o[2*kk  ][lane]);
                u64 wb = pack2(W2e[2*kk+1][lane], W2o[2*kk+1][lane]);
                #pragma unroll
                for (int r = 0; r < RB; ++r) {
                    ulonglong2 iv = *(const ulonglong2*)&t1s[r][4 * kk];
                    a2[r] = ffma2(wa, iv.x, a2[r]);
                    a2[r] = ffma2(wb, iv.y, a2[r]);
                }
            }
            float dh[RB];
            #pragma unroll
            for (int r = 0; r < RB; ++r) dh[r] = tanh_fast(f2_sum(a2[r])) * scale[r];

            // ---- layer 3: t3[j] = tanh(W3[j,:].h_old + b3[j]); h_old in insh[16..47]
            u64 a3[RB], a4[RB];
            #pragma unroll
            for (int r = 0; r < RB; ++r) {
                a3[r] = pack2(bias3a, 0.0f);
                a4[r] = pack2(bias3b, 0.0f);
            }
            #pragma unroll
            for (int kk = 0; kk < 8; ++kk) {
                u64 w0a = pack2(W3e[2*kk  ][lane],      W3o[2*kk  ][lane]);
                u64 w0b = pack2(W3e[2*kk+1][lane],      W3o[2*kk+1][lane]);
                u64 w1a = pack2(W3e[2*kk  ][lane + 32], W3o[2*kk  ][lane + 32]);
                u64 w1b = pack2(W3e[2*kk+1][lane + 32], W3o[2*kk+1][lane + 32]);
                #pragma unroll
                for (int r = 0; r < RB; ++r) {
                    ulonglong2 iv = *(const ulonglong2*)&insh[r][D_IN + 4 * kk];
                    a3[r] = ffma2(w0a, iv.x, a3[r]);
                    a3[r] = ffma2(w0b, iv.y, a3[r]);
                    a4[r] = ffma2(w1a, iv.x, a4[r]);
                    a4[r] = ffma2(w1b, iv.y, a4[r]);
                }
            }

            // ---- layer 4 + state update
            #pragma unroll
            for (int r = 0; r < RB; ++r) {
                float t3a = tanh_fast(f2_sum(a3[r]));
                float t3b = tanh_fast(f2_sum(a4[r]));
                float p = fmaf(w4a, t3a, w4b * t3b);
                p += __shfl_xor_sync(0xffffffffu, p, 16);
                p += __shfl_xor_sync(0xffffffffu, p, 8);
                p += __shfl_xor_sync(0xffffffffu, p, 4);
                p += __shfl_xor_sync(0xffffffffu, p, 2);
                p += __shfl_xor_sync(0xffffffffu, p, 1);
                const float dy = (p + bias4) * scale[r];
                y[r] = fmaf(STEP_F, dy, y[r]);
                h[r] = fmaf(STEP_F, dh[r], h[r]);
            }
            __syncwarp();   // insh/t1s reads done before next-iter writes
        }

        if (lane == 0) {
            #pragma unroll
            for (int r = 0; r < RB; ++r)
                if (b0 + r < B) out[(size_t)(b0 + r) * T_STEPS + t] = y[r];
        }
        __syncwarp();
    }
}

extern "C" void kernel_launch(void* const* d_in, const int* in_sizes, int n_in,
                              void* d_out, int out_size)
{
    const float* dt = (const float*)d_in[0];
    const float* x  = (const float*)d_in[1];
    const float* W1 = (const float*)d_in[2];
    const float* b1 = (const float*)d_in[3];
    const float* W2 = (const float*)d_in[4];
    const float* b2 = (const float*)d_in[5];
    const float* W3 = (const float*)d_in[6];
    const float* b3 = (const float*)d_in[7];
    const float* W4 = (const float*)d_in[8];
    const float* b4 = (const float*)d_in[9];
    float* out = (float*)d_out;

    const int B = in_sizes[1] / (T_STEPS * D_IN);
    const int per_cta = WARPS * RB;
    const int grid = (B + per_cta - 1) / per_cta;
    latode2_kernel<<<grid, WARPS * 32>>>(dt, x, W1, b1, W2, b2, W3, b3,
                                         W4, b4, out, B);
}

// round 6
// speedup vs baseline: 2.8866x; 1.6055x over previous
#include <cuda_runtime.h>

#define T_STEPS 100
#define D_IN 16
#define N_EULER 10
#define DT_SCALER (1.0f/24.0f)
#define STEP_F 0.1f
#define WARPS 8          // warps per CTA (256 threads)
#define RB 7             // batches per warp -> 56 per CTA, grid = 147 <= 148 SMs

typedef unsigned long long u64;

__device__ __forceinline__ float tanh_fast(float v) {
    float r;
    asm("tanh.approx.f32 %0, %1;" : "=f"(r) : "f"(v));
    return r;
}
__device__ __forceinline__ u64 ffma2(u64 a, u64 b, u64 c) {
    u64 d;
    asm("fma.rn.f32x2 %0, %1, %2, %3;" : "=l"(d) : "l"(a), "l"(b), "l"(c));
    return d;
}
__device__ __forceinline__ u64 pack2(float lo, float hi) {
    u64 d;
    asm("mov.b64 %0, {%1, %2};" : "=l"(d) : "f"(lo), "f"(hi));
    return d;
}
__device__ __forceinline__ float f2_sum(u64 v) {
    float lo, hi;
    asm("mov.b64 {%0, %1}, %2;" : "=f"(lo), "=f"(hi) : "l"(v));
    return lo + hi;
}

__global__ void __launch_bounds__(WARPS * 32, 1)
latode2_kernel(const float* __restrict__ dt, const float* __restrict__ x,
               const float* __restrict__ W1, const float* __restrict__ b1,
               const float* __restrict__ W2, const float* __restrict__ b2,
               const float* __restrict__ W3, const float* __restrict__ b3,
               const float* __restrict__ W4, const float* __restrict__ b4,
               float* __restrict__ out, int B)
{
    // SoA even/odd weights: lane j reads column j -> coalesced LDS.32 (1 cyc/wf).
    __shared__ float W1e[24][64], W1o[24][64];   // rows 50..63 zero
    __shared__ float W2e[26][32], W2o[26][32];   // k2=25 zero
    __shared__ float W3e[16][64], W3o[16][64];
    __shared__ float W4s[64], b1s[64], b2s[32], b3s[64];
    __shared__ float b4s;
    __shared__ __align__(16) float in_sh[WARPS][RB][48];   // [x(16) ; h(32)]
    __shared__ __align__(16) float t1_sh[WARPS][RB][64];

    const int tid  = threadIdx.x;
    const int nthr = WARPS * 32;

    for (int i = tid; i < 24 * 64; i += nthr) {
        int k2 = i >> 6, j = i & 63;
        W1e[k2][j] = (j < 50) ? W1[j * 48 + 2 * k2]     : 0.0f;
        W1o[k2][j] = (j < 50) ? W1[j * 48 + 2 * k2 + 1] : 0.0f;
    }
    for (int i = tid; i < 26 * 32; i += nthr) {
        int k2 = i >> 5, j = i & 31;
        W2e[k2][j] = (2 * k2     < 50) ? W2[j * 50 + 2 * k2]     : 0.0f;
        W2o[k2][j] = (2 * k2 + 1 < 50) ? W2[j * 50 + 2 * k2 + 1] : 0.0f;
    }
    for (int i = tid; i < 16 * 64; i += nthr) {
        int k2 = i >> 6, j = i & 63;
        W3e[k2][j] = W3[j * 32 + 2 * k2];
        W3o[k2][j] = W3[j * 32 + 2 * k2 + 1];
    }
    if (tid < 64) {
        W4s[tid] = W4[tid];
        b1s[tid] = (tid < 50) ? b1[tid] : 0.0f;
        b3s[tid] = b3[tid];
    }
    if (tid < 32) b2s[tid] = b2[tid];
    if (tid == 0) b4s = b4[0];
    __syncthreads();

    const int warp = tid >> 5;
    const int lane = tid & 31;
    const int b0   = (blockIdx.x * WARPS + warp) * RB;

    int bi[RB];
    #pragma unroll
    for (int r = 0; r < RB; ++r) {
        int bb = b0 + r;
        bi[r] = (bb < B) ? bb : (B - 1);   // clamp tail: redundant work, valid mem
    }

    float (*insh)[48] = in_sh[warp];
    float (*t1s)[64]  = t1_sh[warp];

    const float bias1a = b1s[lane];
    const float bias1b = b1s[lane + 32];
    const float bias2  = b2s[lane];
    const float bias3a = b3s[lane];
    const float bias3b = b3s[lane + 32];
    const float w4a    = W4s[lane];
    const float w4b    = W4s[lane + 32];
    const float bias4  = b4s;

    float h[RB], y[RB], scale[RB];
    #pragma unroll
    for (int r = 0; r < RB; ++r) h[r] = 0.0f;

    #pragma unroll 1
    for (int t = 0; t < T_STEPS; ++t) {
        #pragma unroll
        for (int r = 0; r < RB; ++r) {
            const float* xr = x + (size_t)bi[r] * T_STEPS * D_IN + (size_t)t * D_IN;
            if (lane < D_IN) insh[r][lane] = xr[lane];
            const float* dr = dt + (size_t)bi[r] * T_STEPS * 2 + (size_t)t * 2;
            scale[r] = (dr[1] - dr[0]) * DT_SCALER;
            y[r] = xr[0];
        }
        __syncwarp();

        // ---- HOISTED layer-1 x-part: constant over the 10 Euler steps.
        // xinit[r] = b1 + W1[:, 0:16] . x[b,t,:]  (scalar floats -> low reg cost)
        float xinit0[RB], xinit1[RB];
        {
            u64 c0[RB], c1[RB];
            #pragma unroll
            for (int r = 0; r < RB; ++r) { c0[r] = 0ULL; c1[r] = 0ULL; }
            #pragma unroll
            for (int kk = 0; kk < 4; ++kk) {
                u64 w0a = pack2(W1e[2*kk  ][lane],      W1o[2*kk  ][lane]);
                u64 w0b = pack2(W1e[2*kk+1][lane],      W1o[2*kk+1][lane]);
                u64 w1a = pack2(W1e[2*kk  ][lane + 32], W1o[2*kk  ][lane + 32]);
                u64 w1b = pack2(W1e[2*kk+1][lane + 32], W1o[2*kk+1][lane + 32]);
                #pragma unroll
                for (int r = 0; r < RB; ++r) {
                    ulonglong2 iv = *(const ulonglong2*)&insh[r][4 * kk];
                    c0[r] = ffma2(w0a, iv.x, c0[r]);
                    c0[r] = ffma2(w0b, iv.y, c0[r]);
                    c1[r] = ffma2(w1a, iv.x, c1[r]);
                    c1[r] = ffma2(w1b, iv.y, c1[r]);
                }
            }
            #pragma unroll
            for (int r = 0; r < RB; ++r) {
                xinit0[r] = f2_sum(c0[r]) + bias1a;
                xinit1[r] = f2_sum(c1[r]) + bias1b;
            }
        }

        #pragma unroll 1
        for (int e = 0; e < N_EULER; ++e) {
            #pragma unroll
            for (int r = 0; r < RB; ++r) insh[r][D_IN + lane] = h[r];  // publish h_old
            __syncwarp();

            // ---- FUSED layer1 h-part + layer3: both read h_old; share iv loads.
            u64 a0[RB], a1[RB], a3[RB], a4[RB];
            #pragma unroll
            for (int r = 0; r < RB; ++r) {
                a0[r] = pack2(xinit0[r], 0.0f);
                a1[r] = pack2(xinit1[r], 0.0f);
                a3[r] = pack2(bias3a, 0.0f);
                a4[r] = pack2(bias3b, 0.0f);
            }
            #pragma unroll
            for (int kk = 0; kk < 8; ++kk) {
                u64 w0a = pack2(W1e[8 + 2*kk  ][lane],      W1o[8 + 2*kk  ][lane]);
                u64 w0b = pack2(W1e[8 + 2*kk+1][lane],      W1o[8 + 2*kk+1][lane]);
                u64 w1a = pack2(W1e[8 + 2*kk  ][lane + 32], W1o[8 + 2*kk  ][lane + 32]);
                u64 w1b = pack2(W1e[8 + 2*kk+1][lane + 32], W1o[8 + 2*kk+1][lane + 32]);
                u64 v0a = pack2(W3e[2*kk  ][lane],      W3o[2*kk  ][lane]);
                u64 v0b = pack2(W3e[2*kk+1][lane],      W3o[2*kk+1][lane]);
                u64 v1a = pack2(W3e[2*kk  ][lane + 32], W3o[2*kk  ][lane + 32]);
                u64 v1b = pack2(W3e[2*kk+1][lane + 32], W3o[2*kk+1][lane + 32]);
                #pragma unroll
                for (int r = 0; r < RB; ++r) {
                    ulonglong2 iv = *(const ulonglong2*)&insh[r][D_IN + 4 * kk];
                    a0[r] = ffma2(w0a, iv.x, a0[r]);
                    a0[r] = ffma2(w0b, iv.y, a0[r]);
                    a1[r] = ffma2(w1a, iv.x, a1[r]);
                    a1[r] = ffma2(w1b, iv.y, a1[r]);
                    a3[r] = ffma2(v0a, iv.x, a3[r]);
                    a3[r] = ffma2(v0b, iv.y, a3[r]);
                    a4[r] = ffma2(v1a, iv.x, a4[r]);
                    a4[r] = ffma2(v1b, iv.y, a4[r]);
                }
            }
            #pragma unroll
            for (int r = 0; r < RB; ++r) {
                t1s[r][lane]      = tanh_fast(f2_sum(a0[r]));
                t1s[r][lane + 32] = tanh_fast(f2_sum(a1[r]));  // pad rows -> 0
            }
            __syncwarp();

            // ---- layer 2: dh[i] = tanh(W2[i,:].t1 + b2[i]) * scale
            u64 a2[RB];
            #pragma unroll
            for (int r = 0; r < RB; ++r) a2[r] = pack2(bias2, 0.0f);
            #pragma unroll
            for (int kk = 0; kk < 13; ++kk) {
                u64 wa = pack2(W2e[2*kk  ][lane], W2o[2*kk  ][lane]);
                u64 wb = pack2(W2e[2*kk+1][lane], W2o[2*kk+1][lane]);
                #pragma unroll
                for (int r = 0; r < RB; ++r) {
                    ulonglong2 iv = *(const ulonglong2*)&t1s[r][4 * kk];
                    a2[r] = ffma2(wa, iv.x, a2[r]);
                    a2[r] = ffma2(wb, iv.y, a2[r]);
                }
            }

            // ---- layer 4 + state update
            #pragma unroll
            for (int r = 0; r < RB; ++r) {
                const float dh = tanh_fast(f2_sum(a2[r])) * scale[r];
                float p = fmaf(w4a, tanh_fast(f2_sum(a3[r])),
                               w4b * tanh_fast(f2_sum(a4[r])));
                p += __shfl_xor_sync(0xffffffffu, p, 16);
                p += __shfl_xor_sync(0xffffffffu, p, 8);
                p += __shfl_xor_sync(0xffffffffu, p, 4);
                p += __shfl_xor_sync(0xffffffffu, p, 2);
                p += __shfl_xor_sync(0xffffffffu, p, 1);
                const float dy = (p + bias4) * scale[r];
                y[r] = fmaf(STEP_F, dy, y[r]);
                h[r] = fmaf(STEP_F, dh, h[r]);
            }
            __syncwarp();   // insh/t1s reads done before next-iter writes
        }

        if (lane == 0) {
            #pragma unroll
            for (int r = 0; r < RB; ++r)
                if (b0 + r < B) out[(size_t)(b0 + r) * T_STEPS + t] = y[r];
        }
        __syncwarp();
    }
}

extern "C" void kernel_launch(void* const* d_in, const int* in_sizes, int n_in,
                              void* d_out, int out_size)
{
    const float* dt = (const float*)d_in[0];
    const float* x  = (const float*)d_in[1];
    const float* W1 = (const float*)d_in[2];
    const float* b1 = (const float*)d_in[3];
    const float* W2 = (const float*)d_in[4];
    const float* b2 = (const float*)d_in[5];
    const float* W3 = (const float*)d_in[6];
    const float* b3 = (const float*)d_in[7];
    const float* W4 = (const float*)d_in[8];
    const float* b4 = (const float*)d_in[9];
    float* out = (float*)d_out;

    const int B = in_sizes[1] / (T_STEPS * D_IN);
    const int per_cta = WARPS * RB;                 // 56
    const int grid = (B + per_cta - 1) / per_cta;   // 147 for B=8192
    latode2_kernel<<<grid, WARPS * 32>>>(dt, x, W1, b1, W2, b2, W3, b3,
                                         W4, b4, out, B);
}

// round 8
// speedup vs baseline: 3.0112x; 1.0432x over previous
#include <cuda_runtime.h>

#define T_STEPS 100
#define D_IN 16
#define N_EULER 10
#define DT_SCALER (1.0f/24.0f)
#define STEP_F 0.1f
#define WARPS 8          // warps per CTA (256 threads)
#define RB 7             // batches per warp -> 56 per CTA, grid = 147 <= 148 SMs

typedef unsigned long long u64;

__device__ __forceinline__ float tanh_fast(float v) {
    float r;
    asm("tanh.approx.f32 %0, %1;" : "=f"(r) : "f"(v));
    return r;
}
__device__ __forceinline__ u64 ffma2(u64 a, u64 b, u64 c) {
    u64 d;
    asm("fma.rn.f32x2 %0, %1, %2, %3;" : "=l"(d) : "l"(a), "l"(b), "l"(c));
    return d;
}
__device__ __forceinline__ u64 pack2(float lo, float hi) {
    u64 d;
    asm("mov.b64 %0, {%1, %2};" : "=l"(d) : "f"(lo), "f"(hi));
    return d;
}
__device__ __forceinline__ float f2_sum(u64 v) {
    float lo, hi;
    asm("mov.b64 {%0, %1}, %2;" : "=f"(lo), "=f"(hi) : "l"(v));
    return lo + hi;
}

__global__ void __launch_bounds__(WARPS * 32, 1)
latode2_kernel(const float* __restrict__ dt, const float* __restrict__ x,
               const float* __restrict__ W1, const float* __restrict__ b1,
               const float* __restrict__ W2, const float* __restrict__ b2,
               const float* __restrict__ W3, const float* __restrict__ b3,
               const float* __restrict__ W4, const float* __restrict__ b4,
               float* __restrict__ out, int B)
{
    // SoA even/odd weights: lane j reads column j -> coalesced LDS.32 (1 cyc/wf).
    __shared__ float W1e[24][64], W1o[24][64];   // rows 50..63 zero
    __shared__ float W2e[26][32], W2o[26][32];   // k2=25 zero
    __shared__ float W3e[16][64], W3o[16][64];
    __shared__ float W4s[64], b1s[64], b2s[32], b3s[64];
    __shared__ float b4s;
    __shared__ __align__(16) float in_sh[WARPS][RB][48];   // [x(16) ; h(32)]
    __shared__ __align__(16) float t1_sh[WARPS][RB][64];

    const int tid  = threadIdx.x;
    const int nthr = WARPS * 32;

    for (int i = tid; i < 24 * 64; i += nthr) {
        int k2 = i >> 6, j = i & 63;
        W1e[k2][j] = (j < 50) ? W1[j * 48 + 2 * k2]     : 0.0f;
        W1o[k2][j] = (j < 50) ? W1[j * 48 + 2 * k2 + 1] : 0.0f;
    }
    for (int i = tid; i < 26 * 32; i += nthr) {
        int k2 = i >> 5, j = i & 31;
        W2e[k2][j] = (2 * k2     < 50) ? W2[j * 50 + 2 * k2]     : 0.0f;
        W2o[k2][j] = (2 * k2 + 1 < 50) ? W2[j * 50 + 2 * k2 + 1] : 0.0f;
    }
    for (int i = tid; i < 16 * 64; i += nthr) {
        int k2 = i >> 6, j = i & 63;
        W3e[k2][j] = W3[j * 32 + 2 * k2];
        W3o[k2][j] = W3[j * 32 + 2 * k2 + 1];
    }
    if (tid < 64) {
        W4s[tid] = W4[tid];
        b1s[tid] = (tid < 50) ? b1[tid] : 0.0f;
        b3s[tid] = b3[tid];
    }
    if (tid < 32) b2s[tid] = b2[tid];
    if (tid == 0) b4s = b4[0];
    __syncthreads();

    const int warp = tid >> 5;
    const int lane = tid & 31;
    const int b0   = (blockIdx.x * WARPS + warp) * RB;

    int bi[RB];
    #pragma unroll
    for (int r = 0; r < RB; ++r) {
        int bb = b0 + r;
        bi[r] = (bb < B) ? bb : (B - 1);   // clamp tail: redundant work, valid mem
    }

    float (*insh)[48] = in_sh[warp];
    float (*t1s)[64]  = t1_sh[warp];

    const float bias1a = b1s[lane];
    const float bias1b = b1s[lane + 32];
    const float bias2  = b2s[lane];
    const float bias3a = b3s[lane];
    const float bias3b = b3s[lane + 32];
    const float w4a    = W4s[lane];
    const float w4b    = W4s[lane + 32];
    const float bias4  = b4s;

    // ---- W3 weights resident in registers: 32 u64 (64 regs), loaded once.
    // Eliminates 8 LDS.32 per kk of the fused loop for all 1000 Euler steps.
    u64 w3r[32];
    #pragma unroll
    for (int kk = 0; kk < 8; ++kk) {
        w3r[4*kk+0] = pack2(W3e[2*kk  ][lane],      W3o[2*kk  ][lane]);
        w3r[4*kk+1] = pack2(W3e[2*kk+1][lane],      W3o[2*kk+1][lane]);
        w3r[4*kk+2] = pack2(W3e[2*kk  ][lane + 32], W3o[2*kk  ][lane + 32]);
        w3r[4*kk+3] = pack2(W3e[2*kk+1][lane + 32], W3o[2*kk+1][lane + 32]);
    }

    float h[RB], y[RB], scale[RB];
    #pragma unroll
    for (int r = 0; r < RB; ++r) h[r] = 0.0f;

    #pragma unroll 1
    for (int t = 0; t < T_STEPS; ++t) {
        #pragma unroll
        for (int r = 0; r < RB; ++r) {
            const float* xr = x + (size_t)bi[r] * T_STEPS * D_IN + (size_t)t * D_IN;
            if (lane < D_IN) insh[r][lane] = xr[lane];
            const float* dr = dt + (size_t)bi[r] * T_STEPS * 2 + (size_t)t * 2;
            scale[r] = (dr[1] - dr[0]) * DT_SCALER;
            y[r] = xr[0];
        }
        __syncwarp();

        // ---- HOISTED layer-1 x-part: constant over the 10 Euler steps.
        float xinit0[RB], xinit1[RB];
        {
            u64 c0[RB], c1[RB];
            #pragma unroll
            for (int r = 0; r < RB; ++r) { c0[r] = 0ULL; c1[r] = 0ULL; }
            #pragma unroll
            for (int kk = 0; kk < 4; ++kk) {
                u64 w0a = pack2(W1e[2*kk  ][lane],      W1o[2*kk  ][lane]);
                u64 w0b = pack2(W1e[2*kk+1][lane],      W1o[2*kk+1][lane]);
                u64 w1a = pack2(W1e[2*kk  ][lane + 32], W1o[2*kk  ][lane + 32]);
                u64 w1b = pack2(W1e[2*kk+1][lane + 32], W1o[2*kk+1][lane + 32]);
                #pragma unroll
                for (int r = 0; r < RB; ++r) {
                    ulonglong2 iv = *(const ulonglong2*)&insh[r][4 * kk];
                    c0[r] = ffma2(w0a, iv.x, c0[r]);
                    c0[r] = ffma2(w0b, iv.y, c0[r]);
                    c1[r] = ffma2(w1a, iv.x, c1[r]);
                    c1[r] = ffma2(w1b, iv.y, c1[r]);
                }
            }
            #pragma unroll
            for (int r = 0; r < RB; ++r) {
                xinit0[r] = f2_sum(c0[r]) + bias1a;
                xinit1[r] = f2_sum(c1[r]) + bias1b;
            }
        }

        #pragma unroll 1
        for (int e = 0; e < N_EULER; ++e) {
            #pragma unroll
            for (int r = 0; r < RB; ++r) insh[r][D_IN + lane] = h[r];  // publish h_old
            __syncwarp();

            // ---- FUSED layer1 h-part + layer3: share h_old iv loads.
            u64 a0[RB], a1[RB], a3[RB], a4[RB];
            #pragma unroll
            for (int r = 0; r < RB; ++r) {
                a0[r] = pack2(xinit0[r], 0.0f);
                a1[r] = pack2(xinit1[r], 0.0f);
                a3[r] = pack2(bias3a, 0.0f);
                a4[r] = pack2(bias3b, 0.0f);
            }
            #pragma unroll
            for (int kk = 0; kk < 8; ++kk) {
                u64 w0a = pack2(W1e[8 + 2*kk  ][lane],      W1o[8 + 2*kk  ][lane]);
                u64 w0b = pack2(W1e[8 + 2*kk+1][lane],      W1o[8 + 2*kk+1][lane]);
                u64 w1a = pack2(W1e[8 + 2*kk  ][lane + 32], W1o[8 + 2*kk  ][lane + 32]);
                u64 w1b = pack2(W1e[8 + 2*kk+1][lane + 32], W1o[8 + 2*kk+1][lane + 32]);
                #pragma unroll
                for (int r = 0; r < RB; ++r) {
                    ulonglong2 iv = *(const ulonglong2*)&insh[r][D_IN + 4 * kk];
                    a0[r] = ffma2(w0a, iv.x, a0[r]);
                    a0[r] = ffma2(w0b, iv.y, a0[r]);
                    a1[r] = ffma2(w1a, iv.x, a1[r]);
                    a1[r] = ffma2(w1b, iv.y, a1[r]);
                    a3[r] = ffma2(w3r[4*kk+0], iv.x, a3[r]);
                    a3[r] = ffma2(w3r[4*kk+1], iv.y, a3[r]);
                    a4[r] = ffma2(w3r[4*kk+2], iv.x, a4[r]);
                    a4[r] = ffma2(w3r[4*kk+3], iv.y, a4[r]);
                }
            }
            #pragma unroll
            for (int r = 0; r < RB; ++r) {
                t1s[r][lane]      = tanh_fast(f2_sum(a0[r]));
                t1s[r][lane + 32] = tanh_fast(f2_sum(a1[r]));  // pad rows -> 0
            }

            // ---- EARLY layer-4: consume a3/a4 now (frees 28 regs before layer 2).
            float py[RB];
            #pragma unroll
            for (int r = 0; r < RB; ++r) {
                float p = fmaf(w4a, tanh_fast(f2_sum(a3[r])),
                               w4b * tanh_fast(f2_sum(a4[r])));
                p += __shfl_xor_sync(0xffffffffu, p, 16);
                p += __shfl_xor_sync(0xffffffffu, p, 8);
                p += __shfl_xor_sync(0xffffffffu, p, 4);
                p += __shfl_xor_sync(0xffffffffu, p, 2);
                p += __shfl_xor_sync(0xffffffffu, p, 1);
                py[r] = p;
            }
            __syncwarp();   // t1s visible to all lanes

            // ---- layer 2: dh[i] = tanh(W2[i,:].t1 + b2[i]) * scale
            u64 a2[RB];
            #pragma unroll
            for (int r = 0; r < RB; ++r) a2[r] = pack2(bias2, 0.0f);
            #pragma unroll
            for (int kk = 0; kk < 13; ++kk) {
                u64 wa = pack2(W2e[2*kk  ][lane], W2o[2*kk  ][lane]);
                u64 wb = pack2(W2e[2*kk+1][lane], W2o[2*kk+1][lane]);
                #pragma unroll
                for (int r = 0; r < RB; ++r) {
                    ulonglong2 iv = *(const ulonglong2*)&t1s[r][4 * kk];
                    a2[r] = ffma2(wa, iv.x, a2[r]);
                    a2[r] = ffma2(wb, iv.y, a2[r]);
                }
            }

            // ---- state update
            #pragma unroll
            for (int r = 0; r < RB; ++r) {
                const float dh = tanh_fast(f2_sum(a2[r])) * scale[r];
                const float dy = (py[r] + bias4) * scale[r];
                y[r] = fmaf(STEP_F, dy, y[r]);
                h[r] = fmaf(STEP_F, dh, h[r]);
            }
            __syncwarp();   // insh/t1s reads done before next-iter writes
        }

        if (lane == 0) {
            #pragma unroll
            for (int r = 0; r < RB; ++r)
                if (b0 + r < B) out[(size_t)(b0 + r) * T_STEPS + t] = y[r];
        }
        __syncwarp();
    }
}

extern "C" void kernel_launch(void* const* d_in, const int* in_sizes, int n_in,
                              void* d_out, int out_size)
{
    const float* dt = (const float*)d_in[0];
    const float* x  = (const float*)d_in[1];
    const float* W1 = (const float*)d_in[2];
    const float* b1 = (const float*)d_in[3];
    const float* W2 = (const float*)d_in[4];
    const float* b2 = (const float*)d_in[5];
    const float* W3 = (const float*)d_in[6];
    const float* b3 = (const float*)d_in[7];
    const float* W4 = (const float*)d_in[8];
    const float* b4 = (const float*)d_in[9];
    float* out = (float*)d_out;

    const int B = in_sizes[1] / (T_STEPS * D_IN);
    const int per_cta = WARPS * RB;                 // 56
    const int grid = (B + per_cta - 1) / per_cta;   // 147 for B=8192
    latode2_kernel<<<grid, WARPS * 32>>>(dt, x, W1, b1, W2, b2, W3, b3,
                                         W4, b4, out, B);
}

// round 11
// speedup vs baseline: 3.0848x; 1.0245x over previous
#include <cuda_runtime.h>

#define T_STEPS 100
#define D_IN 16
#define N_EULER 10
#define DT_SCALER (1.0f/24.0f)
#define STEP_F 0.1f
#define WARPS 8          // warps per CTA (256 threads)
#define RB 7             // batches per warp -> 56 per CTA, grid = 147 <= 148 SMs

typedef unsigned long long u64;

__device__ __forceinline__ float tanh_fast(float v) {
    float r;
    asm("tanh.approx.f32 %0, %1;" : "=f"(r) : "f"(v));
    return r;
}
__device__ __forceinline__ u64 ffma2(u64 a, u64 b, u64 c) {
    u64 d;
    asm("fma.rn.f32x2 %0, %1, %2, %3;" : "=l"(d) : "l"(a), "l"(b), "l"(c));
    return d;
}
__device__ __forceinline__ u64 pack2(float lo, float hi) {
    u64 d;
    asm("mov.b64 %0, {%1, %2};" : "=l"(d) : "f"(lo), "f"(hi));
    return d;
}
__device__ __forceinline__ float f2_sum(u64 v) {
    float lo, hi;
    asm("mov.b64 {%0, %1}, %2;" : "=f"(lo), "=f"(hi) : "l"(v));
    return lo + hi;
}

__global__ void __launch_bounds__(WARPS * 32, 1)
latode2_kernel(const float* __restrict__ dt, const float* __restrict__ x,
               const float* __restrict__ W1, const float* __restrict__ b1,
               const float* __restrict__ W2, const float* __restrict__ b2,
               const float* __restrict__ W3, const float* __restrict__ b3,
               const float* __restrict__ W4, const float* __restrict__ b4,
               float* __restrict__ out, int B)
{
    // SoA even/odd weights: lane j reads column j -> coalesced LDS.32 (1 cyc/wf).
    __shared__ float W1e[24][64], W1o[24][64];   // rows 50..63 zero
    __shared__ float W2e[26][32], W2o[26][32];   // k2=25 zero
    __shared__ float W3e[16][64], W3o[16][64];
    __shared__ float W4s[64], b1s[64], b2s[32], b3s[64];
    __shared__ float b4s;
    __shared__ __align__(16) float in_sh[WARPS][RB][48];   // [x(16) ; h(32)]
    __shared__ __align__(16) float t1_sh[WARPS][RB][64];

    const int tid  = threadIdx.x;
    const int nthr = WARPS * 32;

    for (int i = tid; i < 24 * 64; i += nthr) {
        int k2 = i >> 6, j = i & 63;
        W1e[k2][j] = (j < 50) ? W1[j * 48 + 2 * k2]     : 0.0f;
        W1o[k2][j] = (j < 50) ? W1[j * 48 + 2 * k2 + 1] : 0.0f;
    }
    for (int i = tid; i < 26 * 32; i += nthr) {
        int k2 = i >> 5, j = i & 31;
        W2e[k2][j] = (2 * k2     < 50) ? W2[j * 50 + 2 * k2]     : 0.0f;
        W2o[k2][j] = (2 * k2 + 1 < 50) ? W2[j * 50 + 2 * k2 + 1] : 0.0f;
    }
    for (int i = tid; i < 16 * 64; i += nthr) {
        int k2 = i >> 6, j = i & 63;
        W3e[k2][j] = W3[j * 32 + 2 * k2];
        W3o[k2][j] = W3[j * 32 + 2 * k2 + 1];
    }
    if (tid < 64) {
        W4s[tid] = W4[tid];
        b1s[tid] = (tid < 50) ? b1[tid] : 0.0f;
        b3s[tid] = b3[tid];
    }
    if (tid < 32) b2s[tid] = b2[tid];
    if (tid == 0) b4s = b4[0];
    __syncthreads();

    const int warp = tid >> 5;
    const int lane = tid & 31;
    const int b0   = (blockIdx.x * WARPS + warp) * RB;

    int bi[RB];
    #pragma unroll
    for (int r = 0; r < RB; ++r) {
        int bb = b0 + r;
        bi[r] = (bb < B) ? bb : (B - 1);   // clamp tail: redundant work, valid mem
    }

    float (*insh)[48] = in_sh[warp];
    float (*t1s)[64]  = t1_sh[warp];

    const float bias1a = b1s[lane];
    const float bias1b = b1s[lane + 32];
    const float bias2  = b2s[lane];
    const float bias3a = b3s[lane];
    const float bias3b = b3s[lane + 32];
    const float w4a    = W4s[lane];
    const float w4b    = W4s[lane + 32];
    const float bias4  = b4s;

    // ---- W3 weights resident in registers: 32 u64 (64 regs), loaded once.
    u64 w3r[32];
    #pragma unroll
    for (int kk = 0; kk < 8; ++kk) {
        w3r[4*kk+0] = pack2(W3e[2*kk  ][lane],      W3o[2*kk  ][lane]);
        w3r[4*kk+1] = pack2(W3e[2*kk+1][lane],      W3o[2*kk+1][lane]);
        w3r[4*kk+2] = pack2(W3e[2*kk  ][lane + 32], W3o[2*kk  ][lane + 32]);
        w3r[4*kk+3] = pack2(W3e[2*kk+1][lane + 32], W3o[2*kk+1][lane + 32]);
    }

    float h[RB];
    #pragma unroll
    for (int r = 0; r < RB; ++r) h[r] = 0.0f;

    #pragma unroll 1
    for (int t = 0; t < T_STEPS; ++t) {
        float y0[RB], scale[RB], Pacc[RB];
        #pragma unroll
        for (int r = 0; r < RB; ++r) {
            const float* xr = x + (size_t)bi[r] * T_STEPS * D_IN + (size_t)t * D_IN;
            if (lane < D_IN) insh[r][lane] = xr[lane];
            insh[r][D_IN + lane] = h[r];            // publish h (t=0 init; else refresh)
            const float* dr = dt + (size_t)bi[r] * T_STEPS * 2 + (size_t)t * 2;
            scale[r] = (dr[1] - dr[0]) * DT_SCALER;
            y0[r] = xr[0];
            Pacc[r] = 0.0f;
        }
        __syncwarp();

        // ---- HOISTED layer-1 x-part: constant over the 10 Euler steps.
        float xinit0[RB], xinit1[RB];
        {
            u64 c0[RB], c1[RB];
            #pragma unroll
            for (int r = 0; r < RB; ++r) { c0[r] = 0ULL; c1[r] = 0ULL; }
            #pragma unroll
            for (int kk = 0; kk < 4; ++kk) {
                u64 w0a = pack2(W1e[2*kk  ][lane],      W1o[2*kk  ][lane]);
                u64 w0b = pack2(W1e[2*kk+1][lane],      W1o[2*kk+1][lane]);
                u64 w1a = pack2(W1e[2*kk  ][lane + 32], W1o[2*kk  ][lane + 32]);
                u64 w1b = pack2(W1e[2*kk+1][lane + 32], W1o[2*kk+1][lane + 32]);
                #pragma unroll
                for (int r = 0; r < RB; ++r) {
                    ulonglong2 iv = *(const ulonglong2*)&insh[r][4 * kk];
                    c0[r] = ffma2(w0a, iv.x, c0[r]);
                    c0[r] = ffma2(w0b, iv.y, c0[r]);
                    c1[r] = ffma2(w1a, iv.x, c1[r]);
                    c1[r] = ffma2(w1b, iv.y, c1[r]);
                }
            }
            #pragma unroll
            for (int r = 0; r < RB; ++r) {
                xinit0[r] = f2_sum(c0[r]) + bias1a;
                xinit1[r] = f2_sum(c1[r]) + bias1b;
            }
        }

        #pragma unroll 1
        for (int e = 0; e < N_EULER; ++e) {
            // h_old already published in insh (t-prologue for e=0, end of prev iter else)

            // ---- FUSED layer1 h-part + layer3: share h_old iv loads.
            u64 a0[RB], a1[RB], a3[RB], a4[RB];
            #pragma unroll
            for (int r = 0; r < RB; ++r) {
                a0[r] = pack2(xinit0[r], 0.0f);
                a1[r] = pack2(xinit1[r], 0.0f);
                a3[r] = pack2(bias3a, 0.0f);
                a4[r] = pack2(bias3b, 0.0f);
            }
            #pragma unroll
            for (int kk = 0; kk < 8; ++kk) {
                u64 w0a = pack2(W1e[8 + 2*kk  ][lane],      W1o[8 + 2*kk  ][lane]);
                u64 w0b = pack2(W1e[8 + 2*kk+1][lane],      W1o[8 + 2*kk+1][lane]);
                u64 w1a = pack2(W1e[8 + 2*kk  ][lane + 32], W1o[8 + 2*kk  ][lane + 32]);
                u64 w1b = pack2(W1e[8 + 2*kk+1][lane + 32], W1o[8 + 2*kk+1][lane + 32]);
                #pragma unroll
                for (int r = 0; r < RB; ++r) {
                    ulonglong2 iv = *(const ulonglong2*)&insh[r][D_IN + 4 * kk];
                    a0[r] = ffma2(w0a, iv.x, a0[r]);
                    a0[r] = ffma2(w0b, iv.y, a0[r]);
                    a1[r] = ffma2(w1a, iv.x, a1[r]);
                    a1[r] = ffma2(w1b, iv.y, a1[r]);
                    a3[r] = ffma2(w3r[4*kk+0], iv.x, a3[r]);
                    a3[r] = ffma2(w3r[4*kk+1], iv.y, a3[r]);
                    a4[r] = ffma2(w3r[4*kk+2], iv.x, a4[r]);
                    a4[r] = ffma2(w3r[4*kk+3], iv.y, a4[r]);
                }
            }
            #pragma unroll
            for (int r = 0; r < RB; ++r) {
                t1s[r][lane]      = tanh_fast(f2_sum(a0[r]));
                t1s[r][lane + 32] = tanh_fast(f2_sum(a1[r]));  // pad rows -> 0
            }

            // ---- layer-4 partial: per-lane accumulate only; the cross-lane
            // shfl reduction is DEFERRED to once per time step (y does not
            // feed back into the dynamics; scale is constant over Euler steps).
            #pragma unroll
            for (int r = 0; r < RB; ++r) {
                Pacc[r] += fmaf(w4a, tanh_fast(f2_sum(a3[r])),
                                w4b * tanh_fast(f2_sum(a4[r])));
            }
            __syncwarp();   // t1s visible to all lanes

            // ---- layer 2: dh[i] = tanh(W2[i,:].t1 + b2[i]) * scale
            u64 a2[RB];
            #pragma unroll
            for (int r = 0; r < RB; ++r) a2[r] = pack2(bias2, 0.0f);
            #pragma unroll
            for (int kk = 0; kk < 13; ++kk) {
                u64 wa = pack2(W2e[2*kk  ][lane], W2o[2*kk  ][lane]);
                u64 wb = pack2(W2e[2*kk+1][lane], W2o[2*kk+1][lane]);
                #pragma unroll
                for (int r = 0; r < RB; ++r) {
                    ulonglong2 iv = *(const ulonglong2*)&t1s[r][4 * kk];
                    a2[r] = ffma2(wa, iv.x, a2[r]);
                    a2[r] = ffma2(wb, iv.y, a2[r]);
                }
            }

            // ---- state update + publish h for next iteration (merged sync)
            #pragma unroll
            for (int r = 0; r < RB; ++r) {
                const float dh = tanh_fast(f2_sum(a2[r])) * scale[r];
                h[r] = fmaf(STEP_F, dh, h[r]);
                insh[r][D_IN + lane] = h[r];
            }
            __syncwarp();   // covers: t1s reads done + new h visible
        }

        // ---- Deferred layer-4 reduction + output, once per time step:
        // y_final = y0 + STEP * scale * (sum_lanes(Pacc) + 10*b4)
        #pragma unroll
        for (int r = 0; r < RB; ++r) {
            float S = Pacc[r];
            S += __shfl_xor_sync(0xffffffffu, S, 16);
            S += __shfl_xor_sync(0xffffffffu, S, 8);
            S += __shfl_xor_sync(0xffffffffu, S, 4);
            S += __shfl_xor_sync(0xffffffffu, S, 2);
            S += __shfl_xor_sync(0xffffffffu, S, 1);
            if (lane == 0 && b0 + r < B) {
                float yv = fmaf(STEP_F * scale[r], S + (float)N_EULER * bias4, y0[r]);
                out[(size_t)(b0 + r) * T_STEPS + t] = yv;
            }
        }
        __syncwarp();
    }
}

extern "C" void kernel_launch(void* const* d_in, const int* in_sizes, int n_in,
                              void* d_out, int out_size)
{
    const float* dt = (const float*)d_in[0];
    const float* x  = (const float*)d_in[1];
    const float* W1 = (const float*)d_in[2];
    const float* b1 = (const float*)d_in[3];
    const float* W2 = (const float*)d_in[4];
    const float* b2 = (const float*)d_in[5];
    const float* W3 = (const float*)d_in[6];
    const float* b3 = (const float*)d_in[7];
    const float* W4 = (const float*)d_in[8];
    const float* b4 = (const float*)d_in[9];
    float* out = (float*)d_out;

    const int B = in_sizes[1] / (T_STEPS * D_IN);
    const int per_cta = WARPS * RB;                 // 56
    const int grid = (B + per_cta - 1) / per_cta;   // 147 for B=8192
    latode2_kernel<<<grid, WARPS * 32>>>(dt, x, W1, b1, W2, b2, W3, b3,
                                         W4, b4, out, B);
}

// round 14
// speedup vs baseline: 3.0943x; 1.0031x over previous
#include <cuda_runtime.h>

#define T_STEPS 100
#define D_IN 16
#define N_EULER 10
#define DT_SCALER (1.0f/24.0f)
#define STEP_F 0.1f
#define WARPS 8          // warps per CTA (256 threads)
#define RB 7             // batches per warp -> 56 per CTA, grid = 147 <= 148 SMs

typedef unsigned long long u64;

__device__ __forceinline__ float tanh_fast(float v) {
    float r;
    asm("tanh.approx.f32 %0, %1;" : "=f"(r) : "f"(v));
    return r;
}
__device__ __forceinline__ u64 ffma2(u64 a, u64 b, u64 c) {
    u64 d;
    asm("fma.rn.f32x2 %0, %1, %2, %3;" : "=l"(d) : "l"(a), "l"(b), "l"(c));
    return d;
}
__device__ __forceinline__ u64 pack2(float lo, float hi) {
    u64 d;
    asm("mov.b64 %0, {%1, %2};" : "=l"(d) : "f"(lo), "f"(hi));
    return d;
}
__device__ __forceinline__ float f2_sum(u64 v) {
    float lo, hi;
    asm("mov.b64 {%0, %1}, %2;" : "=f"(lo), "=f"(hi) : "l"(v));
    return lo + hi;
}

__global__ void __launch_bounds__(WARPS * 32, 1)
latode2_kernel(const float* __restrict__ dt, const float* __restrict__ x,
               const float* __restrict__ W1, const float* __restrict__ b1,
               const float* __restrict__ W2, const float* __restrict__ b2,
               const float* __restrict__ W3, const float* __restrict__ b3,
               const float* __restrict__ W4, const float* __restrict__ b4,
               float* __restrict__ out, int B)
{
    // SoA even/odd weights: lane j reads column j -> coalesced LDS.32 (1 cyc/wf).
    __shared__ float W1e[24][64], W1o[24][64];   // rows 50..63 zero
    __shared__ float W2e[25][32], W2o[25][32];   // k2 = 0..24 (k 0..49), no pad pair
    __shared__ float W3e[16][64], W3o[16][64];
    __shared__ float W4s[64], b1s[64], b2s[32], b3s[64];
    __shared__ float b4s;
    __shared__ __align__(16) float in_sh[WARPS][RB][48];   // [x(16) ; h(32)]
    __shared__ __align__(16) float t1_sh[WARPS][RB][64];

    const int tid  = threadIdx.x;
    const int nthr = WARPS * 32;

    for (int i = tid; i < 24 * 64; i += nthr) {
        int k2 = i >> 6, j = i & 63;
        W1e[k2][j] = (j < 50) ? W1[j * 48 + 2 * k2]     : 0.0f;
        W1o[k2][j] = (j < 50) ? W1[j * 48 + 2 * k2 + 1] : 0.0f;
    }
    for (int i = tid; i < 25 * 32; i += nthr) {
        int k2 = i / 32, j = i & 31;
        W2e[k2][j] = W2[j * 50 + 2 * k2];
        W2o[k2][j] = W2[j * 50 + 2 * k2 + 1];
    }
    for (int i = tid; i < 16 * 64; i += nthr) {
        int k2 = i >> 6, j = i & 63;
        W3e[k2][j] = W3[j * 32 + 2 * k2];
        W3o[k2][j] = W3[j * 32 + 2 * k2 + 1];
    }
    if (tid < 64) {
        W4s[tid] = W4[tid];
        b1s[tid] = (tid < 50) ? b1[tid] : 0.0f;
        b3s[tid] = b3[tid];
    }
    if (tid < 32) b2s[tid] = b2[tid];
    if (tid == 0) b4s = b4[0];
    __syncthreads();

    const int warp = tid >> 5;
    const int lane = tid & 31;
    const int b0   = (blockIdx.x * WARPS + warp) * RB;

    float (*insh)[48] = in_sh[warp];
    float (*t1s)[64]  = t1_sh[warp];

    const float bias1a = b1s[lane];
    const float bias1b = b1s[lane + 32];
    const float bias2  = b2s[lane];
    const float bias3a = b3s[lane];
    const float bias3b = b3s[lane + 32];
    const float w4a    = W4s[lane];
    const float w4b    = W4s[lane + 32];
    const float bias4  = b4s;

    // ---- W3 weights resident in registers: 32 u64 (64 regs), loaded once.
    u64 w3r[32];
    #pragma unroll
    for (int kk = 0; kk < 8; ++kk) {
        w3r[4*kk+0] = pack2(W3e[2*kk  ][lane],      W3o[2*kk  ][lane]);
        w3r[4*kk+1] = pack2(W3e[2*kk+1][lane],      W3o[2*kk+1][lane]);
        w3r[4*kk+2] = pack2(W3e[2*kk  ][lane + 32], W3o[2*kk  ][lane + 32]);
        w3r[4*kk+3] = pack2(W3e[2*kk+1][lane + 32], W3o[2*kk+1][lane + 32]);
    }

    float h[RB];
    #pragma unroll
    for (int r = 0; r < RB; ++r) h[r] = 0.0f;

    #pragma unroll 1
    for (int t = 0; t < T_STEPS; ++t) {
        float scale[RB], Pacc[RB];
        #pragma unroll
        for (int r = 0; r < RB; ++r) {
            int bb = b0 + r; bb = (bb < B) ? bb : (B - 1);   // clamp inline (ALU only)
            const float* xr = x + (size_t)bb * T_STEPS * D_IN + (size_t)t * D_IN;
            if (lane < D_IN) insh[r][lane] = xr[lane];
            insh[r][D_IN + lane] = h[r];            // publish h (t=0 init; else refresh)
            const float* dr = dt + (size_t)bb * T_STEPS * 2 + (size_t)t * 2;
            scale[r] = (dr[1] - dr[0]) * DT_SCALER;
            Pacc[r] = 0.0f;
        }
        __syncwarp();

        // ---- HOISTED layer-1 x-part: constant over the 10 Euler steps.
        float xinit0[RB], xinit1[RB];
        {
            u64 c0[RB], c1[RB];
            #pragma unroll
            for (int r = 0; r < RB; ++r) { c0[r] = 0ULL; c1[r] = 0ULL; }
            #pragma unroll
            for (int kk = 0; kk < 4; ++kk) {
                u64 w0a = pack2(W1e[2*kk  ][lane],      W1o[2*kk  ][lane]);
                u64 w0b = pack2(W1e[2*kk+1][lane],      W1o[2*kk+1][lane]);
                u64 w1a = pack2(W1e[2*kk  ][lane + 32], W1o[2*kk  ][lane + 32]);
                u64 w1b = pack2(W1e[2*kk+1][lane + 32], W1o[2*kk+1][lane + 32]);
                #pragma unroll
                for (int r = 0; r < RB; ++r) {
                    ulonglong2 iv = *(const ulonglong2*)&insh[r][4 * kk];
                    c0[r] = ffma2(w0a, iv.x, c0[r]);
                    c0[r] = ffma2(w0b, iv.y, c0[r]);
                    c1[r] = ffma2(w1a, iv.x, c1[r]);
                    c1[r] = ffma2(w1b, iv.y, c1[r]);
                }
            }
            #pragma unroll
            for (int r = 0; r < RB; ++r) {
                xinit0[r] = f2_sum(c0[r]) + bias1a;
                xinit1[r] = f2_sum(c1[r]) + bias1b;
            }
        }

        #pragma unroll 1
        for (int e = 0; e < N_EULER; ++e) {
            // h_old already published in insh (t-prologue for e=0, end of prev iter else)

            // ---- FUSED layer1 h-part + layer3: share h_old iv loads.
            u64 a0[RB], a1[RB], a3[RB], a4[RB];
            #pragma unroll
            for (int r = 0; r < RB; ++r) {
                a0[r] = pack2(xinit0[r], 0.0f);
                a1[r] = pack2(xinit1[r], 0.0f);
                a3[r] = pack2(bias3a, 0.0f);
                a4[r] = pack2(bias3b, 0.0f);
            }
            #pragma unroll
            for (int kk = 0; kk < 8; ++kk) {
                u64 w0a = pack2(W1e[8 + 2*kk  ][lane],      W1o[8 + 2*kk  ][lane]);
                u64 w0b = pack2(W1e[8 + 2*kk+1][lane],      W1o[8 + 2*kk+1][lane]);
                u64 w1a = pack2(W1e[8 + 2*kk  ][lane + 32], W1o[8 + 2*kk  ][lane + 32]);
                u64 w1b = pack2(W1e[8 + 2*kk+1][lane + 32], W1o[8 + 2*kk+1][lane + 32]);
                #pragma unroll
                for (int r = 0; r < RB; ++r) {
                    ulonglong2 iv = *(const ulonglong2*)&insh[r][D_IN + 4 * kk];
                    a0[r] = ffma2(w0a, iv.x, a0[r]);
                    a0[r] = ffma2(w0b, iv.y, a0[r]);
                    a1[r] = ffma2(w1a, iv.x, a1[r]);
                    a1[r] = ffma2(w1b, iv.y, a1[r]);
                    a3[r] = ffma2(w3r[4*kk+0], iv.x, a3[r]);
                    a3[r] = ffma2(w3r[4*kk+1], iv.y, a3[r]);
                    a4[r] = ffma2(w3r[4*kk+2], iv.x, a4[r]);
                    a4[r] = ffma2(w3r[4*kk+3], iv.y, a4[r]);
                }
            }
            #pragma unroll
            for (int r = 0; r < RB; ++r) {
                t1s[r][lane]      = tanh_fast(f2_sum(a0[r]));
                t1s[r][lane + 32] = tanh_fast(f2_sum(a1[r]));  // pad rows -> 0
            }

            // ---- layer-4 partial: per-lane accumulate; cross-lane reduction
            // deferred to once per time step (y never feeds the dynamics).
            #pragma unroll
            for (int r = 0; r < RB; ++r) {
                Pacc[r] += fmaf(w4a, tanh_fast(f2_sum(a3[r])),
                                w4b * tanh_fast(f2_sum(a4[r])));
            }
            __syncwarp();   // t1s visible to all lanes

            // ---- layer 2: dh[i] = tanh(W2[i,:].t1 + b2[i]) * scale
            // k = 0..47 via 12 full kk, k = 48..49 via one LDS.64 tail (no pad pair).
            u64 a2[RB];
            #pragma unroll
            for (int r = 0; r < RB; ++r) a2[r] = pack2(bias2, 0.0f);
            #pragma unroll
            for (int kk = 0; kk < 12; ++kk) {
                u64 wa = pack2(W2e[2*kk  ][lane], W2o[2*kk  ][lane]);
                u64 wb = pack2(W2e[2*kk+1][lane], W2o[2*kk+1][lane]);
                #pragma unroll
                for (int r = 0; r < RB; ++r) {
                    ulonglong2 iv = *(const ulonglong2*)&t1s[r][4 * kk];
                    a2[r] = ffma2(wa, iv.x, a2[r]);
                    a2[r] = ffma2(wb, iv.y, a2[r]);
                }
            }
            {
                u64 wt = pack2(W2e[24][lane], W2o[24][lane]);
                #pragma unroll
                for (int r = 0; r < RB; ++r) {
                    u64 iv = *(const u64*)&t1s[r][48];
                    a2[r] = ffma2(wt, iv, a2[r]);
                }
            }

            // ---- state update + publish h for next iteration (merged sync)
            #pragma unroll
            for (int r = 0; r < RB; ++r) {
                const float dh = tanh_fast(f2_sum(a2[r])) * scale[r];
                h[r] = fmaf(STEP_F, dh, h[r]);
                insh[r][D_IN + lane] = h[r];
            }
            __syncwarp();   // covers: t1s reads done + new h visible
        }

        // ---- Deferred layer-4 reduction + output, once per time step:
        // y_final = x[b,t,0] + STEP * scale * (sum_lanes(Pacc) + 10*b4)
        #pragma unroll
        for (int r = 0; r < RB; ++r) {
            float S = Pacc[r];
            S += __shfl_xor_sync(0xffffffffu, S, 16);
            S += __shfl_xor_sync(0xffffffffu, S, 8);
            S += __shfl_xor_sync(0xffffffffu, S, 4);
            S += __shfl_xor_sync(0xffffffffu, S, 2);
            S += __shfl_xor_sync(0xffffffffu, S, 1);
            if (lane == 0 && b0 + r < B) {
                float y0v = x[(size_t)(b0 + r) * T_STEPS * D_IN + (size_t)t * D_IN];
                float yv = fmaf(STEP_F * scale[r], S + (float)N_EULER * bias4, y0v);
                out[(size_t)(b0 + r) * T_STEPS + t] = yv;
            }
        }
        // no trailing syncwarp: shfl_xor is self-synchronizing, and all insh
        // reads completed before the final Euler-step syncwarp above.
    }
}

extern "C" void kernel_launch(void* const* d_in, const int* in_sizes, int n_in,
                              void* d_out, int out_size)
{
    const float* dt = (const float*)d_in[0];
    const float* x  = (const float*)d_in[1];
    const float* W1 = (const float*)d_in[2];
    const float* b1 = (const float*)d_in[3];
    const float* W2 = (const float*)d_in[4];
    const float* b2 = (const float*)d_in[5];
    const float* W3 = (const float*)d_in[6];
    const float* b3 = (const float*)d_in[7];
    const float* W4 = (const float*)d_in[8];
    const float* b4 = (const float*)d_in[9];
    float* out = (float*)d_out;

    const int B = in_sizes[1] / (T_STEPS * D_IN);
    const int per_cta = WARPS * RB;                 // 56
    const int grid = (B + per_cta - 1) / per_cta;   // 147 for B=8192
    latode2_kernel<<<grid, WARPS * 32>>>(dt, x, W1, b1, W2, b2, W3, b3,
                                         W4, b4, out, B);
}